// round 16
// baseline (speedup 1.0000x reference)
#include <cuda_runtime.h>
#include <cuda_bf16.h>
#include <cstdint>

// ---------------- problem constants ----------------
#define TOK    32768
#define BHW    8192
#define NSEG   4
#define INDIM  1536
#define HID    768
#define NHEAD  8
#define HD     96

// int8 two-digit scales:  a ~= S*(A1/128 + A2/32768)
#define SX  8.0f     // x and attention-output magnitudes (|v| <= ~6 sigma of N(0,1)-ish)
#define SW  0.16f    // weight magnitudes (0.02 * N(0,1))
#define F1Q (SX*SW/16384.0f)     // digit1*digit1 scale
#define F2Q (SX*SW/4194304.0f)   // cross-digit scale (2^-22)

// ---------------- scratch ----------------
__device__ float g_q[(size_t)TOK * HID];
__device__ float g_k[(size_t)TOK * HID];
__device__ float g_v[(size_t)TOK * HID];
// x in token layout, int8 digits
__device__ signed char g_x1[(size_t)TOK * INDIM];
__device__ signed char g_x2[(size_t)TOK * INDIM];
// attention output, int8 digits
__device__ signed char g_o1[(size_t)TOK * HID];
__device__ signed char g_o2[(size_t)TOK * HID];
// transposed weights [n][k], int8 digits
__device__ signed char g_wq1[(size_t)HID * INDIM];
__device__ signed char g_wq2[(size_t)HID * INDIM];
__device__ signed char g_wk1[(size_t)HID * INDIM];
__device__ signed char g_wk2[(size_t)HID * INDIM];
__device__ signed char g_wv1[(size_t)HID * INDIM];
__device__ signed char g_wv2[(size_t)HID * INDIM];
__device__ signed char g_wo1[(size_t)INDIM * HID];
__device__ signed char g_wo2[(size_t)INDIM * HID];

// ---------------- helpers ----------------
__device__ __forceinline__ uint32_t smem_u32(const void* p) {
    uint32_t a;
    asm("{ .reg .u64 t; cvta.to.shared.u64 t, %1; cvt.u32.u64 %0, t; }" : "=r"(a) : "l"(p));
    return a;
}

__device__ __forceinline__ void cp16(uint32_t dst, const void* src) {
    asm volatile("cp.async.cg.shared.global [%0], [%1], 16;" :: "r"(dst), "l"(src) : "memory");
}
#define CP_COMMIT() asm volatile("cp.async.commit_group;" ::: "memory")
#define CP_WAIT(n)  asm volatile("cp.async.wait_group %0;" :: "n"(n) : "memory")

#define LDSM_X4(r, a) \
    asm volatile("ldmatrix.sync.aligned.m8n8.x4.shared.b16 {%0,%1,%2,%3}, [%4];" \
        : "=r"((r)[0]), "=r"((r)[1]), "=r"((r)[2]), "=r"((r)[3]) : "r"(a))

// int8 k32 MMA: byte-layout of fragments identical to f16 k16, so the same
// LDSM addressing yields correct s8 fragments.
__device__ __forceinline__ void mma_s8(int* d, const uint32_t* a, uint32_t b0, uint32_t b1) {
    asm volatile("mma.sync.aligned.m16n8k32.row.col.s32.s8.s8.s32 "
        "{%0,%1,%2,%3}, {%4,%5,%6,%7}, {%8,%9}, {%0,%1,%2,%3};"
        : "+r"(d[0]), "+r"(d[1]), "+r"(d[2]), "+r"(d[3])
        : "r"(a[0]), "r"(a[1]), "r"(a[2]), "r"(a[3]), "r"(b0), "r"(b1));
}

__device__ __forceinline__ void quant2(float v, float s, signed char& d1, signed char& d2) {
    int a1 = __float2int_rn(v * (128.0f / s));
    a1 = max(-127, min(127, a1));
    float r = v - (float)a1 * (s * 0.0078125f);   // s/128
    int a2 = __float2int_rn(r * (32768.0f / s));
    a2 = max(-127, min(127, a2));
    d1 = (signed char)a1;
    d2 = (signed char)a2;
}

// =====================================================================
// conversions (one-time per launch)
// =====================================================================
__global__ void convert_x(const float* __restrict__ x)
{
    size_t i2 = (size_t)blockIdx.x * 256 + threadIdx.x;
    size_t idx = i2 * 2;
    int d  = (int)(idx & 63);
    int hw = (int)((idx >> 6) & 1023);
    int r  = (int)(idx >> 16);        // b*96 + t
    int t  = r % 96, b = r / 96;
    int sg = t / 24, p = t - sg * 24;
    int m  = ((b * 1024 + hw) << 2) + sg;
    int k  = p * 64 + d;
    float2 v = *(const float2*)(x + idx);
    signed char a1, a2, b1, b2;
    quant2(v.x, SX, a1, a2);
    quant2(v.y, SX, b1, b2);
    size_t o = (size_t)m * INDIM + k;
    *(char2*)(g_x1 + o) = make_char2(a1, b1);
    *(char2*)(g_x2 + o) = make_char2(a2, b2);
}

__global__ void convert_qkv(const float* __restrict__ Wq,
                            const float* __restrict__ Wk,
                            const float* __restrict__ Wv)
{
    const int z = blockIdx.y;
    const float* W = (z == 0) ? Wq : ((z == 1) ? Wk : Wv);
    signed char* o1 = (z == 0) ? g_wq1 : ((z == 1) ? g_wk1 : g_wv1);
    signed char* o2 = (z == 0) ? g_wq2 : ((z == 1) ? g_wk2 : g_wv2);
    int idx = blockIdx.x * 256 + threadIdx.x;      // n*INDIM + k
    int n = idx / INDIM, k = idx - n * INDIM;
    float v = W[(size_t)k * HID + n];
    signed char d1, d2;
    quant2(v, SW, d1, d2);
    o1[idx] = d1;
    o2[idx] = d2;
}

__global__ void convert_wo(const float* __restrict__ Wo)
{
    int idx = blockIdx.x * 256 + threadIdx.x;      // e*HID + k
    int e = idx / HID, k = idx - e * HID;
    float v = Wo[(size_t)k * INDIM + e];
    signed char d1, d2;
    quant2(v, SW, d1, d2);
    g_wo1[idx] = d1;
    g_wo2[idx] = d2;
}

// =====================================================================
// Kernel 1: QKV GEMM, int8 two-digit, 3 integer passes.
// CTA tile 128(M)x64(N), K-chunk 32 (32 bytes), 3 stages, 256 threads.
// grid (12, 256, 3).
// =====================================================================
__global__ __launch_bounds__(256, 2) void gemm_qkv_i8()
{
    __shared__ signed char sA1[3][128][48];   // 32 data bytes + 16 pad (conflict-free LDSM)
    __shared__ signed char sA2[3][128][48];
    __shared__ signed char sB1[3][64][48];
    __shared__ signed char sB2[3][64][48];

    const int tid = threadIdx.x;
    const int n0 = blockIdx.x * 64, m0 = blockIdx.y * 128, z = blockIdx.z;
    const signed char* W1 = (z == 0) ? g_wq1 : ((z == 1) ? g_wk1 : g_wv1);
    const signed char* W2 = (z == 0) ? g_wq2 : ((z == 1) ? g_wk2 : g_wv2);
    float* C = (z == 0) ? g_q : ((z == 1) ? g_k : g_v);

    // loader: A (row = tid>>1, 16B half = tid&1) covers both digit planes;
    //         B (row = tid>>2, half = (tid>>1)&1, plane = tid&1)
    const int arow = tid >> 1, ahB = (tid & 1) * 16;
    const int brow = tid >> 2, bhB = ((tid >> 1) & 1) * 16, bgrp = tid & 1;
    const signed char* as1 = g_x1 + (size_t)(m0 + arow) * INDIM + ahB;
    const signed char* as2 = g_x2 + (size_t)(m0 + arow) * INDIM + ahB;
    const signed char* bs  = (bgrp ? W2 : W1) + (size_t)(n0 + brow) * INDIM + bhB;

    const int wid = tid >> 5, lane = tid & 31;
    const int wm = wid & 3, wn = wid >> 2;
    const int aldr = wm * 32 + (lane & 15);
    const int aldB = (lane >> 4) * 16;                         // byte offset in row
    const int bldr = wn * 32 + ((lane >> 4) & 1) * 8 + (lane & 7);
    const int bldB = ((lane >> 3) & 1) * 16;

    int acc1[2][4][4], acc2[2][4][4];
    #pragma unroll
    for (int mi = 0; mi < 2; mi++)
        #pragma unroll
        for (int ni = 0; ni < 4; ni++)
            #pragma unroll
            for (int q = 0; q < 4; q++) { acc1[mi][ni][q] = 0; acc2[mi][ni][q] = 0; }

    const int NC = INDIM / 32;   // 48

    #define STAGE(st, c) do {                                                 \
        cp16(smem_u32(&sA1[st][arow][ahB]), as1 + (c) * 32);                  \
        cp16(smem_u32(&sA2[st][arow][ahB]), as2 + (c) * 32);                  \
        cp16(smem_u32(&(bgrp ? sB2 : sB1)[st][brow][bhB]), bs + (c) * 32);    \
    } while (0)

    STAGE(0, 0); CP_COMMIT();
    STAGE(1, 1); CP_COMMIT();

    int sc_ = 0;
    for (int c = 0; c < NC; c++) {
        CP_WAIT(1);
        __syncthreads();
        int sn = sc_ + 2; if (sn >= 3) sn -= 3;
        if (c + 2 < NC) { STAGE(sn, c + 2); CP_COMMIT(); }

        uint32_t a1[2][4], a2[2][4], b1[2][4], b2[2][4];
        #pragma unroll
        for (int mi = 0; mi < 2; mi++) {
            LDSM_X4(a1[mi], smem_u32(&sA1[sc_][aldr + mi * 16][aldB]));
            LDSM_X4(a2[mi], smem_u32(&sA2[sc_][aldr + mi * 16][aldB]));
        }
        #pragma unroll
        for (int g = 0; g < 2; g++) {
            LDSM_X4(b1[g], smem_u32(&sB1[sc_][bldr + g * 16][bldB]));
            LDSM_X4(b2[g], smem_u32(&sB2[sc_][bldr + g * 16][bldB]));
        }
        // pass 1: digit1 x digit1  -> acc1
        #pragma unroll
        for (int mi = 0; mi < 2; mi++)
            #pragma unroll
            for (int ni = 0; ni < 4; ni++)
                mma_s8(acc1[mi][ni], a1[mi],
                       b1[ni >> 1][(ni & 1) * 2], b1[ni >> 1][(ni & 1) * 2 + 1]);
        // pass 2+3: cross digits (same scale) -> acc2
        #pragma unroll
        for (int mi = 0; mi < 2; mi++)
            #pragma unroll
            for (int ni = 0; ni < 4; ni++)
                mma_s8(acc2[mi][ni], a1[mi],
                       b2[ni >> 1][(ni & 1) * 2], b2[ni >> 1][(ni & 1) * 2 + 1]);
        #pragma unroll
        for (int mi = 0; mi < 2; mi++)
            #pragma unroll
            for (int ni = 0; ni < 4; ni++)
                mma_s8(acc2[mi][ni], a2[mi],
                       b1[ni >> 1][(ni & 1) * 2], b1[ni >> 1][(ni & 1) * 2 + 1]);
        if (++sc_ == 3) sc_ = 0;
    }
    #undef STAGE

    // epilogue: fold scales, contiguous fp32 stores
    #pragma unroll
    for (int mi = 0; mi < 2; mi++) {
        int r = m0 + wm * 32 + mi * 16 + (lane >> 2);
        #pragma unroll
        for (int ni = 0; ni < 4; ni++) {
            int cg = n0 + wn * 32 + ni * 8 + (lane & 3) * 2;
            float v0 = F1Q * __int2float_rn(acc1[mi][ni][0]) + F2Q * __int2float_rn(acc2[mi][ni][0]);
            float v1 = F1Q * __int2float_rn(acc1[mi][ni][1]) + F2Q * __int2float_rn(acc2[mi][ni][1]);
            float v2 = F1Q * __int2float_rn(acc1[mi][ni][2]) + F2Q * __int2float_rn(acc2[mi][ni][2]);
            float v3 = F1Q * __int2float_rn(acc1[mi][ni][3]) + F2Q * __int2float_rn(acc2[mi][ni][3]);
            *(float2*)(C + (size_t)r * HID + cg)       = make_float2(v0, v1);
            *(float2*)(C + (size_t)(r + 8) * HID + cg) = make_float2(v2, v3);
        }
    }
}

// =====================================================================
// Kernel 2: RoPE + tiny attention; emits o as int8 digits.
// =====================================================================
__global__ __launch_bounds__(256)
void attn_kernel(const float* __restrict__ fcos, const float* __restrict__ fsin)
{
    __shared__ float sq[NSEG][HID];
    __shared__ float sk[NSEG][HID];
    __shared__ float sv[NSEG][HID];

    const int bhw = blockIdx.x;
    const int tid = threadIdx.x;
    const long base = (long)bhw * NSEG * HID;

    for (int idx = tid; idx < NSEG * (HID / 2); idx += 256) {
        int i = idx / (HID / 2);
        int j = idx - i * (HID / 2);
        float c = fcos[i * (HID / 2) + j];
        float s = fsin[i * (HID / 2) + j];
        float2 q2 = *(const float2*)(g_q + base + (long)i * HID + 2 * j);
        float2 k2 = *(const float2*)(g_k + base + (long)i * HID + 2 * j);
        sq[i][2 * j]     = q2.x * c - q2.y * s;
        sq[i][2 * j + 1] = q2.x * s + q2.y * c;
        sk[i][2 * j]     = k2.x * c - k2.y * s;
        sk[i][2 * j + 1] = k2.x * s + k2.y * c;
        float2 v2 = *(const float2*)(g_v + base + (long)i * HID + 2 * j);
        *(float2*)&sv[i][2 * j] = v2;
    }
    __syncthreads();

    const int w = tid >> 5;
    const int lane = tid & 31;
    const int cb = w * HD;

    float sc[4][4];
    #pragma unroll
    for (int i = 0; i < 4; i++)
        #pragma unroll
        for (int j = 0; j < 4; j++) {
            float p = 0.f;
            #pragma unroll
            for (int t = 0; t < 3; t++) {
                int d = lane + 32 * t;
                p += sq[i][cb + d] * sk[j][cb + d];
            }
            sc[i][j] = p;
        }
    #pragma unroll
    for (int i = 0; i < 4; i++)
        #pragma unroll
        for (int j = 0; j < 4; j++)
            #pragma unroll
            for (int off = 16; off > 0; off >>= 1)
                sc[i][j] += __shfl_xor_sync(0xffffffffu, sc[i][j], off);

    const float scale = 0.10206207261596577f;   // 1/sqrt(96)
    float attn[4][4];
    #pragma unroll
    for (int i = 0; i < 4; i++) {
        float mx = -1e30f;
        #pragma unroll
        for (int j = 0; j < 4; j++) { sc[i][j] *= scale; mx = fmaxf(mx, sc[i][j]); }
        float sum = 0.f;
        #pragma unroll
        for (int j = 0; j < 4; j++) { attn[i][j] = expf(sc[i][j] - mx); sum += attn[i][j]; }
        float inv = 1.f / sum;
        #pragma unroll
        for (int j = 0; j < 4; j++) attn[i][j] *= inv;
    }

    #pragma unroll
    for (int i = 0; i < 4; i++) {
        #pragma unroll
        for (int t = 0; t < 3; t++) {
            int d = lane + 32 * t;
            float o = 0.f;
            #pragma unroll
            for (int j = 0; j < 4; j++) o += attn[i][j] * sv[j][cb + d];
            long oi = base + (long)i * HID + cb + d;
            signed char d1, d2;
            quant2(o, SX, d1, d2);
            g_o1[oi] = d1;
            g_o2[oi] = d2;
        }
    }
}

// =====================================================================
// Kernel 3: O-proj GEMM, int8 two-digit, 3 integer passes.
// CTA tile 128x64, K-chunk 32, 3 stages, 256 threads.  grid (24, 256).
// =====================================================================
__global__ __launch_bounds__(256, 2) void gemm_o_i8(const float* __restrict__ bo,
                                                    float* __restrict__ out)
{
    __shared__ signed char sA1[3][128][48];
    __shared__ signed char sA2[3][128][48];
    __shared__ signed char sB1[3][64][48];
    __shared__ signed char sB2[3][64][48];

    const int tid = threadIdx.x;
    const int n0 = blockIdx.x * 64, m0 = blockIdx.y * 128;

    const int arow = tid >> 1, ahB = (tid & 1) * 16;
    const int brow = tid >> 2, bhB = ((tid >> 1) & 1) * 16, bgrp = tid & 1;
    const signed char* as1 = g_o1 + (size_t)(m0 + arow) * HID + ahB;
    const signed char* as2 = g_o2 + (size_t)(m0 + arow) * HID + ahB;
    const signed char* bs  = (bgrp ? g_wo2 : g_wo1) + (size_t)(n0 + brow) * HID + bhB;

    const int wid = tid >> 5, lane = tid & 31;
    const int wm = wid & 3, wn = wid >> 2;
    const int aldr = wm * 32 + (lane & 15);
    const int aldB = (lane >> 4) * 16;
    const int bldr = wn * 32 + ((lane >> 4) & 1) * 8 + (lane & 7);
    const int bldB = ((lane >> 3) & 1) * 16;

    int acc1[2][4][4], acc2[2][4][4];
    #pragma unroll
    for (int mi = 0; mi < 2; mi++)
        #pragma unroll
        for (int ni = 0; ni < 4; ni++)
            #pragma unroll
            for (int q = 0; q < 4; q++) { acc1[mi][ni][q] = 0; acc2[mi][ni][q] = 0; }

    const int NC = HID / 32;   // 24

    #define STAGE(st, c) do {                                                 \
        cp16(smem_u32(&sA1[st][arow][ahB]), as1 + (c) * 32);                  \
        cp16(smem_u32(&sA2[st][arow][ahB]), as2 + (c) * 32);                  \
        cp16(smem_u32(&(bgrp ? sB2 : sB1)[st][brow][bhB]), bs + (c) * 32);    \
    } while (0)

    STAGE(0, 0); CP_COMMIT();
    STAGE(1, 1); CP_COMMIT();

    int sc_ = 0;
    for (int c = 0; c < NC; c++) {
        CP_WAIT(1);
        __syncthreads();
        int sn = sc_ + 2; if (sn >= 3) sn -= 3;
        if (c + 2 < NC) { STAGE(sn, c + 2); CP_COMMIT(); }

        uint32_t a1[2][4], a2[2][4], b1[2][4], b2[2][4];
        #pragma unroll
        for (int mi = 0; mi < 2; mi++) {
            LDSM_X4(a1[mi], smem_u32(&sA1[sc_][aldr + mi * 16][aldB]));
            LDSM_X4(a2[mi], smem_u32(&sA2[sc_][aldr + mi * 16][aldB]));
        }
        #pragma unroll
        for (int g = 0; g < 2; g++) {
            LDSM_X4(b1[g], smem_u32(&sB1[sc_][bldr + g * 16][bldB]));
            LDSM_X4(b2[g], smem_u32(&sB2[sc_][bldr + g * 16][bldB]));
        }
        #pragma unroll
        for (int mi = 0; mi < 2; mi++)
            #pragma unroll
            for (int ni = 0; ni < 4; ni++)
                mma_s8(acc1[mi][ni], a1[mi],
                       b1[ni >> 1][(ni & 1) * 2], b1[ni >> 1][(ni & 1) * 2 + 1]);
        #pragma unroll
        for (int mi = 0; mi < 2; mi++)
            #pragma unroll
            for (int ni = 0; ni < 4; ni++)
                mma_s8(acc2[mi][ni], a1[mi],
                       b2[ni >> 1][(ni & 1) * 2], b2[ni >> 1][(ni & 1) * 2 + 1]);
        #pragma unroll
        for (int mi = 0; mi < 2; mi++)
            #pragma unroll
            for (int ni = 0; ni < 4; ni++)
                mma_s8(acc2[mi][ni], a2[mi],
                       b1[ni >> 1][(ni & 1) * 2], b1[ni >> 1][(ni & 1) * 2 + 1]);
        if (++sc_ == 3) sc_ = 0;
    }
    #undef STAGE

    // epilogue: fold scales, + bias, scatter to (B,T,H,W,D)
    #pragma unroll
    for (int mi = 0; mi < 2; mi++) {
        #pragma unroll
        for (int half = 0; half < 2; half++) {
            int m = m0 + wm * 32 + mi * 16 + (lane >> 2) + half * 8;
            int bhw = m >> 2, sg = m & 3, b = bhw >> 10, hw = bhw & 1023;
            long baseO = ((long)(b * 96 + sg * 24) * 1024 + hw) * 64;
            #pragma unroll
            for (int ni = 0; ni < 4; ni++) {
                int e = n0 + wn * 32 + ni * 8 + (lane & 3) * 2;
                int p = e >> 6, d = e & 63;
                float2 bb = *(const float2*)(bo + e);
                float v0 = F1Q * __int2float_rn(acc1[mi][ni][half * 2])
                         + F2Q * __int2float_rn(acc2[mi][ni][half * 2]) + bb.x;
                float v1 = F1Q * __int2float_rn(acc1[mi][ni][half * 2 + 1])
                         + F2Q * __int2float_rn(acc2[mi][ni][half * 2 + 1]) + bb.y;
                *(float2*)(out + baseO + (long)p * 65536 + d) = make_float2(v0, v1);
            }
        }
    }
}

// =====================================================================
extern "C" void kernel_launch(void* const* d_in, const int* in_sizes, int n_in,
                              void* d_out, int out_size)
{
    const float* x  = (const float*)d_in[0];
    const float* fc = (const float*)d_in[1];
    const float* fs = (const float*)d_in[2];
    const float* Wq = (const float*)d_in[3];
    const float* Wk = (const float*)d_in[4];
    const float* Wv = (const float*)d_in[5];
    const float* Wo = (const float*)d_in[6];
    const float* bo = (const float*)d_in[7];
    float* out = (float*)d_out;

    convert_qkv<<<dim3((HID * INDIM) / 256, 3), 256>>>(Wq, Wk, Wv);
    convert_wo<<<(INDIM * HID) / 256, 256>>>(Wo);
    convert_x<<<(TOK * (size_t)INDIM / 2) / 256, 256>>>(x);
    gemm_qkv_i8<<<dim3(HID / 64, TOK / 128, 3), 256>>>();
    attn_kernel<<<BHW, 256>>>(fc, fs);
    gemm_o_i8<<<dim3(INDIM / 64, TOK / 128), 256>>>(bo, out);
}

// round 17
// speedup vs baseline: 1.9765x; 1.9765x over previous
#include <cuda_runtime.h>
#include <cuda_fp16.h>
#include <cstdint>

// ---------------- problem constants ----------------
#define TOK    32768
#define BHW    8192
#define NSEG   4
#define INDIM  1536
#define HID    768
#define NHEAD  8
#define HD     96

// Karatsuba-2 combine coefficients:  D = C1*P1 + C2*E
#define C2K 0.0009765625f          // 2^-10
#define C1K (1.0f - C2K)

// ---------------- scratch ----------------
__device__ float g_q[(size_t)TOK * HID];
__device__ float g_k[(size_t)TOK * HID];
__device__ float g_v[(size_t)TOK * HID];
// x in token layout, fp16 planes: p1 = fp16(a), p2 = fp16(p1 + 1024*(a-p1))
__device__ __half g_x1[(size_t)TOK * INDIM];
__device__ __half g_x2[(size_t)TOK * INDIM];
// attention output planes
__device__ __half g_o1[(size_t)TOK * HID];
__device__ __half g_o2[(size_t)TOK * HID];
// transposed weights [n][k], fp16 planes
__device__ __half g_wq1[(size_t)HID * INDIM];
__device__ __half g_wq2[(size_t)HID * INDIM];
__device__ __half g_wk1[(size_t)HID * INDIM];
__device__ __half g_wk2[(size_t)HID * INDIM];
__device__ __half g_wv1[(size_t)HID * INDIM];
__device__ __half g_wv2[(size_t)HID * INDIM];
__device__ __half g_wo1[(size_t)INDIM * HID];
__device__ __half g_wo2[(size_t)INDIM * HID];

// ---------------- helpers ----------------
__device__ __forceinline__ uint32_t smem_u32(const void* p) {
    uint32_t a;
    asm("{ .reg .u64 t; cvta.to.shared.u64 t, %1; cvt.u32.u64 %0, t; }" : "=r"(a) : "l"(p));
    return a;
}

__device__ __forceinline__ void cp16(uint32_t dst, const void* src) {
    asm volatile("cp.async.cg.shared.global [%0], [%1], 16;" :: "r"(dst), "l"(src) : "memory");
}
#define CP_COMMIT() asm volatile("cp.async.commit_group;" ::: "memory")
#define CP_WAIT(n)  asm volatile("cp.async.wait_group %0;" :: "n"(n) : "memory")

#define LDSM_X4(r, a) \
    asm volatile("ldmatrix.sync.aligned.m8n8.x4.shared.b16 {%0,%1,%2,%3}, [%4];" \
        : "=r"((r)[0]), "=r"((r)[1]), "=r"((r)[2]), "=r"((r)[3]) : "r"(a))

__device__ __forceinline__ void mma_f16(float* d, const uint32_t* a, uint32_t b0, uint32_t b1) {
    asm volatile("mma.sync.aligned.m16n8k16.row.col.f32.f16.f16.f32 "
        "{%0,%1,%2,%3}, {%4,%5,%6,%7}, {%8,%9}, {%0,%1,%2,%3};"
        : "+f"(d[0]), "+f"(d[1]), "+f"(d[2]), "+f"(d[3])
        : "r"(a[0]), "r"(a[1]), "r"(a[2]), "r"(a[3]), "r"(b0), "r"(b1));
}

// plane split: p1 = fp16(v); p2 = fp16(float(p1) + 1024*(v - float(p1)))
__device__ __forceinline__ void splitk(float v, __half& p1, __half& p2) {
    __half h = __float2half_rn(v);
    float hf = __half2float(h);
    p1 = h;
    p2 = __float2half_rn(hf + 1024.0f * (v - hf));
}

// =====================================================================
// conversions (one-time per launch)
// =====================================================================
__global__ void convert_x(const float* __restrict__ x)
{
    size_t i2 = (size_t)blockIdx.x * 256 + threadIdx.x;
    size_t idx = i2 * 2;
    int d  = (int)(idx & 63);
    int hw = (int)((idx >> 6) & 1023);
    int r  = (int)(idx >> 16);        // b*96 + t
    int t  = r % 96, b = r / 96;
    int sg = t / 24, p = t - sg * 24;
    int m  = ((b * 1024 + hw) << 2) + sg;
    int k  = p * 64 + d;
    float2 v = *(const float2*)(x + idx);
    __half a1, a2, b1, b2;
    splitk(v.x, a1, a2);
    splitk(v.y, b1, b2);
    size_t o = (size_t)m * INDIM + k;
    *(__half2*)(g_x1 + o) = __halves2half2(a1, b1);
    *(__half2*)(g_x2 + o) = __halves2half2(a2, b2);
}

__global__ void convert_qkv(const float* __restrict__ Wq,
                            const float* __restrict__ Wk,
                            const float* __restrict__ Wv)
{
    const int z = blockIdx.y;
    const float* W = (z == 0) ? Wq : ((z == 1) ? Wk : Wv);
    __half* o1 = (z == 0) ? g_wq1 : ((z == 1) ? g_wk1 : g_wv1);
    __half* o2 = (z == 0) ? g_wq2 : ((z == 1) ? g_wk2 : g_wv2);
    int idx = blockIdx.x * 256 + threadIdx.x;      // n*INDIM + k
    int n = idx / INDIM, k = idx - n * INDIM;
    float v = W[(size_t)k * HID + n];
    __half p1, p2;
    splitk(v, p1, p2);
    o1[idx] = p1;
    o2[idx] = p2;
}

__global__ void convert_wo(const float* __restrict__ Wo)
{
    int idx = blockIdx.x * 256 + threadIdx.x;      // e*HID + k
    int e = idx / HID, k = idx - e * HID;
    float v = Wo[(size_t)k * INDIM + e];
    __half p1, p2;
    splitk(v, p1, p2);
    g_wo1[idx] = p1;
    g_wo2[idx] = p2;
}

// =====================================================================
// Kernel 1: QKV GEMM, fp16 Karatsuba-2 (2 MMA passes).
// CTA tile 128(M)x64(N), K-chunk 16, 3 stages, 256 threads.
// grid (12, 256, 3).
// =====================================================================
__global__ __launch_bounds__(256, 2) void gemm_qkv_mma()
{
    __shared__ __half sA1[3][128][24];
    __shared__ __half sA2[3][128][24];
    __shared__ __half sB1[3][64][24];
    __shared__ __half sB2[3][64][24];

    const int tid = threadIdx.x;
    const int n0 = blockIdx.x * 64, m0 = blockIdx.y * 128, z = blockIdx.z;
    const __half* W1 = (z == 0) ? g_wq1 : ((z == 1) ? g_wk1 : g_wv1);
    const __half* W2 = (z == 0) ? g_wq2 : ((z == 1) ? g_wk2 : g_wv2);
    float* C = (z == 0) ? g_q : ((z == 1) ? g_k : g_v);

    const int arow = tid >> 1, ahalf = tid & 1;
    const int brow = tid >> 2, bhalf = (tid >> 1) & 1, bgrp = tid & 1;
    const __half* as1 = g_x1 + (size_t)(m0 + arow) * INDIM + ahalf * 8;
    const __half* as2 = g_x2 + (size_t)(m0 + arow) * INDIM + ahalf * 8;
    const __half* bs  = (bgrp ? W2 : W1) + (size_t)(n0 + brow) * INDIM + bhalf * 8;

    const int wid = tid >> 5, lane = tid & 31;
    const int wm = wid & 3, wn = wid >> 2;
    const int aldr = wm * 32 + (lane & 15);
    const int aldc = (lane >> 4) * 8;
    const int bldr = wn * 32 + ((lane >> 4) & 1) * 8 + (lane & 7);
    const int bldc = ((lane >> 3) & 1) * 8;

    float acc1[2][4][4], acc2[2][4][4];
    #pragma unroll
    for (int mi = 0; mi < 2; mi++)
        #pragma unroll
        for (int ni = 0; ni < 4; ni++)
            #pragma unroll
            for (int q = 0; q < 4; q++) { acc1[mi][ni][q] = 0.f; acc2[mi][ni][q] = 0.f; }

    const int NC = INDIM / 16;   // 96

    #define STAGE(st, c) do {                                                     \
        cp16(smem_u32(&sA1[st][arow][ahalf * 8]), as1 + (c) * 16);                \
        cp16(smem_u32(&sA2[st][arow][ahalf * 8]), as2 + (c) * 16);                \
        cp16(smem_u32(&(bgrp ? sB2 : sB1)[st][brow][bhalf * 8]), bs + (c) * 16);  \
    } while (0)

    STAGE(0, 0); CP_COMMIT();
    STAGE(1, 1); CP_COMMIT();

    int sc_ = 0;
    for (int c = 0; c < NC; c++) {
        CP_WAIT(1);
        __syncthreads();
        int sn = sc_ + 2; if (sn >= 3) sn -= 3;
        if (c + 2 < NC) { STAGE(sn, c + 2); CP_COMMIT(); }

        uint32_t a1[2][4], a2[2][4], b1[2][4], b2[2][4];
        #pragma unroll
        for (int mi = 0; mi < 2; mi++) {
            LDSM_X4(a1[mi], smem_u32(&sA1[sc_][aldr + mi * 16][aldc]));
            LDSM_X4(a2[mi], smem_u32(&sA2[sc_][aldr + mi * 16][aldc]));
        }
        #pragma unroll
        for (int g = 0; g < 2; g++) {
            LDSM_X4(b1[g], smem_u32(&sB1[sc_][bldr + g * 16][bldc]));
            LDSM_X4(b2[g], smem_u32(&sB2[sc_][bldr + g * 16][bldc]));
        }
        // pass 1: plane1 x plane1 -> acc1 (P1)
        #pragma unroll
        for (int mi = 0; mi < 2; mi++)
            #pragma unroll
            for (int ni = 0; ni < 4; ni++)
                mma_f16(acc1[mi][ni], a1[mi],
                        b1[ni >> 1][(ni & 1) * 2], b1[ni >> 1][(ni & 1) * 2 + 1]);
        // pass 2: plane2 x plane2 -> acc2 (E)
        #pragma unroll
        for (int mi = 0; mi < 2; mi++)
            #pragma unroll
            for (int ni = 0; ni < 4; ni++)
                mma_f16(acc2[mi][ni], a2[mi],
                        b2[ni >> 1][(ni & 1) * 2], b2[ni >> 1][(ni & 1) * 2 + 1]);
        if (++sc_ == 3) sc_ = 0;
    }
    #undef STAGE

    // epilogue: D = C1*P1 + C2*E, contiguous fp32 stores
    #pragma unroll
    for (int mi = 0; mi < 2; mi++) {
        int r = m0 + wm * 32 + mi * 16 + (lane >> 2);
        #pragma unroll
        for (int ni = 0; ni < 4; ni++) {
            int cg = n0 + wn * 32 + ni * 8 + (lane & 3) * 2;
            float v0 = C1K * acc1[mi][ni][0] + C2K * acc2[mi][ni][0];
            float v1 = C1K * acc1[mi][ni][1] + C2K * acc2[mi][ni][1];
            float v2 = C1K * acc1[mi][ni][2] + C2K * acc2[mi][ni][2];
            float v3 = C1K * acc1[mi][ni][3] + C2K * acc2[mi][ni][3];
            *(float2*)(C + (size_t)r * HID + cg)       = make_float2(v0, v1);
            *(float2*)(C + (size_t)(r + 8) * HID + cg) = make_float2(v2, v3);
        }
    }
}

// =====================================================================
// Kernel 2: RoPE + tiny attention; emits o as fp16 planes.
// =====================================================================
__global__ __launch_bounds__(256)
void attn_kernel(const float* __restrict__ fcos, const float* __restrict__ fsin)
{
    __shared__ float sq[NSEG][HID];
    __shared__ float sk[NSEG][HID];
    __shared__ float sv[NSEG][HID];

    const int bhw = blockIdx.x;
    const int tid = threadIdx.x;
    const long base = (long)bhw * NSEG * HID;

    for (int idx = tid; idx < NSEG * (HID / 2); idx += 256) {
        int i = idx / (HID / 2);
        int j = idx - i * (HID / 2);
        float c = fcos[i * (HID / 2) + j];
        float s = fsin[i * (HID / 2) + j];
        float2 q2 = *(const float2*)(g_q + base + (long)i * HID + 2 * j);
        float2 k2 = *(const float2*)(g_k + base + (long)i * HID + 2 * j);
        sq[i][2 * j]     = q2.x * c - q2.y * s;
        sq[i][2 * j + 1] = q2.x * s + q2.y * c;
        sk[i][2 * j]     = k2.x * c - k2.y * s;
        sk[i][2 * j + 1] = k2.x * s + k2.y * c;
        float2 v2 = *(const float2*)(g_v + base + (long)i * HID + 2 * j);
        *(float2*)&sv[i][2 * j] = v2;
    }
    __syncthreads();

    const int w = tid >> 5;
    const int lane = tid & 31;
    const int cb = w * HD;

    float sc[4][4];
    #pragma unroll
    for (int i = 0; i < 4; i++)
        #pragma unroll
        for (int j = 0; j < 4; j++) {
            float p = 0.f;
            #pragma unroll
            for (int t = 0; t < 3; t++) {
                int d = lane + 32 * t;
                p += sq[i][cb + d] * sk[j][cb + d];
            }
            sc[i][j] = p;
        }
    #pragma unroll
    for (int i = 0; i < 4; i++)
        #pragma unroll
        for (int j = 0; j < 4; j++)
            #pragma unroll
            for (int off = 16; off > 0; off >>= 1)
                sc[i][j] += __shfl_xor_sync(0xffffffffu, sc[i][j], off);

    const float scale = 0.10206207261596577f;   // 1/sqrt(96)
    float attn[4][4];
    #pragma unroll
    for (int i = 0; i < 4; i++) {
        float mx = -1e30f;
        #pragma unroll
        for (int j = 0; j < 4; j++) { sc[i][j] *= scale; mx = fmaxf(mx, sc[i][j]); }
        float sum = 0.f;
        #pragma unroll
        for (int j = 0; j < 4; j++) { attn[i][j] = expf(sc[i][j] - mx); sum += attn[i][j]; }
        float inv = 1.f / sum;
        #pragma unroll
        for (int j = 0; j < 4; j++) attn[i][j] *= inv;
    }

    #pragma unroll
    for (int i = 0; i < 4; i++) {
        #pragma unroll
        for (int t = 0; t < 3; t++) {
            int d = lane + 32 * t;
            float o = 0.f;
            #pragma unroll
            for (int j = 0; j < 4; j++) o += attn[i][j] * sv[j][cb + d];
            long oi = base + (long)i * HID + cb + d;
            __half p1, p2;
            splitk(o, p1, p2);
            g_o1[oi] = p1;
            g_o2[oi] = p2;
        }
    }
}

// =====================================================================
// Kernel 3: O-proj GEMM, fp16 Karatsuba-2.
// CTA tile 128x64, K-chunk 16, 3 stages, 256 threads.  grid (24, 256).
// =====================================================================
__global__ __launch_bounds__(256, 2) void gemm_o_mma(const float* __restrict__ bo,
                                                     float* __restrict__ out)
{
    __shared__ __half sA1[3][128][24];
    __shared__ __half sA2[3][128][24];
    __shared__ __half sB1[3][64][24];
    __shared__ __half sB2[3][64][24];

    const int tid = threadIdx.x;
    const int n0 = blockIdx.x * 64, m0 = blockIdx.y * 128;

    const int arow = tid >> 1, ahalf = tid & 1;
    const int brow = tid >> 2, bhalf = (tid >> 1) & 1, bgrp = tid & 1;
    const __half* as1 = g_o1 + (size_t)(m0 + arow) * HID + ahalf * 8;
    const __half* as2 = g_o2 + (size_t)(m0 + arow) * HID + ahalf * 8;
    const __half* bs  = (bgrp ? g_wo2 : g_wo1) + (size_t)(n0 + brow) * HID + bhalf * 8;

    const int wid = tid >> 5, lane = tid & 31;
    const int wm = wid & 3, wn = wid >> 2;
    const int aldr = wm * 32 + (lane & 15);
    const int aldc = (lane >> 4) * 8;
    const int bldr = wn * 32 + ((lane >> 4) & 1) * 8 + (lane & 7);
    const int bldc = ((lane >> 3) & 1) * 8;

    float acc1[2][4][4], acc2[2][4][4];
    #pragma unroll
    for (int mi = 0; mi < 2; mi++)
        #pragma unroll
        for (int ni = 0; ni < 4; ni++)
            #pragma unroll
            for (int q = 0; q < 4; q++) { acc1[mi][ni][q] = 0.f; acc2[mi][ni][q] = 0.f; }

    const int NC = HID / 16;   // 48

    #define STAGE(st, c) do {                                                     \
        cp16(smem_u32(&sA1[st][arow][ahalf * 8]), as1 + (c) * 16);                \
        cp16(smem_u32(&sA2[st][arow][ahalf * 8]), as2 + (c) * 16);                \
        cp16(smem_u32(&(bgrp ? sB2 : sB1)[st][brow][bhalf * 8]), bs + (c) * 16);  \
    } while (0)

    STAGE(0, 0); CP_COMMIT();
    STAGE(1, 1); CP_COMMIT();

    int sc_ = 0;
    for (int c = 0; c < NC; c++) {
        CP_WAIT(1);
        __syncthreads();
        int sn = sc_ + 2; if (sn >= 3) sn -= 3;
        if (c + 2 < NC) { STAGE(sn, c + 2); CP_COMMIT(); }

        uint32_t a1[2][4], a2[2][4], b1[2][4], b2[2][4];
        #pragma unroll
        for (int mi = 0; mi < 2; mi++) {
            LDSM_X4(a1[mi], smem_u32(&sA1[sc_][aldr + mi * 16][aldc]));
            LDSM_X4(a2[mi], smem_u32(&sA2[sc_][aldr + mi * 16][aldc]));
        }
        #pragma unroll
        for (int g = 0; g < 2; g++) {
            LDSM_X4(b1[g], smem_u32(&sB1[sc_][bldr + g * 16][bldc]));
            LDSM_X4(b2[g], smem_u32(&sB2[sc_][bldr + g * 16][bldc]));
        }
        #pragma unroll
        for (int mi = 0; mi < 2; mi++)
            #pragma unroll
            for (int ni = 0; ni < 4; ni++)
                mma_f16(acc1[mi][ni], a1[mi],
                        b1[ni >> 1][(ni & 1) * 2], b1[ni >> 1][(ni & 1) * 2 + 1]);
        #pragma unroll
        for (int mi = 0; mi < 2; mi++)
            #pragma unroll
            for (int ni = 0; ni < 4; ni++)
                mma_f16(acc2[mi][ni], a2[mi],
                        b2[ni >> 1][(ni & 1) * 2], b2[ni >> 1][(ni & 1) * 2 + 1]);
        if (++sc_ == 3) sc_ = 0;
    }
    #undef STAGE

    // epilogue: D = C1*P1 + C2*E + bias, scatter to (B,T,H,W,D)
    #pragma unroll
    for (int mi = 0; mi < 2; mi++) {
        #pragma unroll
        for (int half = 0; half < 2; half++) {
            int m = m0 + wm * 32 + mi * 16 + (lane >> 2) + half * 8;
            int bhw = m >> 2, sg = m & 3, b = bhw >> 10, hw = bhw & 1023;
            long baseO = ((long)(b * 96 + sg * 24) * 1024 + hw) * 64;
            #pragma unroll
            for (int ni = 0; ni < 4; ni++) {
                int e = n0 + wn * 32 + ni * 8 + (lane & 3) * 2;
                int p = e >> 6, d = e & 63;
                float2 bb = *(const float2*)(bo + e);
                float v0 = C1K * acc1[mi][ni][half * 2]     + C2K * acc2[mi][ni][half * 2]     + bb.x;
                float v1 = C1K * acc1[mi][ni][half * 2 + 1] + C2K * acc2[mi][ni][half * 2 + 1] + bb.y;
                *(float2*)(out + baseO + (long)p * 65536 + d) = make_float2(v0, v1);
            }
        }
    }
}

// =====================================================================
extern "C" void kernel_launch(void* const* d_in, const int* in_sizes, int n_in,
                              void* d_out, int out_size)
{
    const float* x  = (const float*)d_in[0];
    const float* fc = (const float*)d_in[1];
    const float* fs = (const float*)d_in[2];
    const float* Wq = (const float*)d_in[3];
    const float* Wk = (const float*)d_in[4];
    const float* Wv = (const float*)d_in[5];
    const float* Wo = (const float*)d_in[6];
    const float* bo = (const float*)d_in[7];
    float* out = (float*)d_out;

    convert_qkv<<<dim3((HID * INDIM) / 256, 3), 256>>>(Wq, Wk, Wv);
    convert_wo<<<(INDIM * HID) / 256, 256>>>(Wo);
    convert_x<<<(TOK * (size_t)INDIM / 2) / 256, 256>>>(x);
    gemm_qkv_mma<<<dim3(HID / 64, TOK / 128, 3), 256>>>();
    attn_kernel<<<BHW, 256>>>(fc, fs);
    gemm_o_mma<<<dim3(INDIM / 64, TOK / 128), 256>>>(bo, out);
}